// round 11
// baseline (speedup 1.0000x reference)
#include <cuda_runtime.h>
#include <cuda_fp16.h>
#include <math.h>
#include <stdint.h>

// Problem constants (fixed: b=2, h=w=256, DIM=256, HEADS=8, 8x8 windows)
#define DIMC 256
#define NHEADS 8
#define HD 32
#define WSZ 64
#define MAXB 2

// Scratch (allocation-free rule: __device__ globals)
__device__ __half g_qkvh[(size_t)MAXB * 65536 * 768]; // QKV output (fp16)
__device__ __half g_y[(size_t)MAXB * 65536 * 256];    // attention output (fp16)
__device__ __half g_xh[(size_t)MAXB * 65536 * 256];   // x in fp16
__device__ __half g_wqkvh[768 * 256];                 // wqkv_w fp16
__device__ __half g_wph[256 * 256];                   // wp_w fp16

// ---------------------------------------------------------------------------
// helpers
// ---------------------------------------------------------------------------
__device__ __forceinline__ void cp16(uint32_t saddr, const void* g) {
    asm volatile("cp.async.cg.shared.global [%0], [%1], 16;" :: "r"(saddr), "l"(g));
}
__device__ __forceinline__ void mma16816(float* d, const uint32_t* a,
                                         const uint32_t* b) {
    asm volatile(
        "mma.sync.aligned.m16n8k16.row.col.f32.f16.f16.f32 "
        "{%0,%1,%2,%3}, {%4,%5,%6,%7}, {%8,%9}, {%0,%1,%2,%3};"
        : "+f"(d[0]), "+f"(d[1]), "+f"(d[2]), "+f"(d[3])
        : "r"(a[0]), "r"(a[1]), "r"(a[2]), "r"(a[3]), "r"(b[0]), "r"(b[1]));
}
__device__ __forceinline__ void ldsm4(uint32_t* r, uint32_t addr) {
    asm volatile("ldmatrix.sync.aligned.m8n8.x4.shared.b16 {%0,%1,%2,%3}, [%4];"
                 : "=r"(r[0]), "=r"(r[1]), "=r"(r[2]), "=r"(r[3]) : "r"(addr));
}
__device__ __forceinline__ void ldsm4t(uint32_t* r, uint32_t addr) {
    asm volatile("ldmatrix.sync.aligned.m8n8.x4.trans.shared.b16 {%0,%1,%2,%3}, [%4];"
                 : "=r"(r[0]), "=r"(r[1]), "=r"(r[2]), "=r"(r[3]) : "r"(addr));
}
__device__ __forceinline__ void ldsm2(uint32_t* r, uint32_t addr) {
    asm volatile("ldmatrix.sync.aligned.m8n8.x2.shared.b16 {%0,%1}, [%2];"
                 : "=r"(r[0]), "=r"(r[1]) : "r"(addr));
}
__device__ __forceinline__ uint32_t packh2(float x, float y) {
    __half2 h = __floats2half2_rn(x, y);
    return *reinterpret_cast<uint32_t*>(&h);
}

// fp32 -> fp16 convert
__global__ void f2h_convert_kernel(const float* __restrict__ in,
                                   __half* __restrict__ out, int n4) {
    int i = blockIdx.x * blockDim.x + threadIdx.x;
    if (i < n4) {
        float4 v = reinterpret_cast<const float4*>(in)[i];
        uint2 p;
        p.x = packh2(v.x, v.y);
        p.y = packh2(v.z, v.w);
        reinterpret_cast<uint2*>(out)[i] = p;
    }
}

// ---------------------------------------------------------------------------
// FP16 tensor-core GEMM, fp32 accum, fused bias, templated output type:
//   C[M,N] = A[M,K](f16) * W[N,K](f16)^T + bias[N](f32)
// 128x128x64 tile, 8 warps (2x4), warp tile 64x32 via 4x4 m16n8k16.
// 3-stage cp.async ring, ldmatrix loads, fragment double-buffering.
// ---------------------------------------------------------------------------
#define GBM 128
#define GBN 128
#define GBK 64
#define PADH 72
#define NSTAGE 3
#define GEMM_SMEM (NSTAGE * (GBM + GBN) * PADH * 2)  // 110592 bytes

template <typename OutT>
__global__ __launch_bounds__(256, 2)
void gemm_f16_kernel(const __half* __restrict__ A, const __half* __restrict__ W,
                     const float* __restrict__ bias, OutT* __restrict__ C,
                     int M, int N, int K) {
    extern __shared__ __half smh[];
    __half* As = smh;                          // [NSTAGE][GBM][PADH]
    __half* Bs = smh + NSTAGE * GBM * PADH;    // [NSTAGE][GBN][PADH]

    const int tid = threadIdx.x;
    const int lane = tid & 31;
    const int warp = tid >> 5;
    const int wm = warp >> 2;  // 0..1
    const int wn = warp & 3;   // 0..3
    const long m0 = (long)blockIdx.y * GBM;
    const long n0 = (long)blockIdx.x * GBN;

    const uint32_t sAu = (uint32_t)__cvta_generic_to_shared(As);
    const uint32_t sBu = (uint32_t)__cvta_generic_to_shared(Bs);

    float acc[4][4][4];
#pragma unroll
    for (int mt = 0; mt < 4; mt++)
#pragma unroll
        for (int nt = 0; nt < 4; nt++)
#pragma unroll
            for (int r = 0; r < 4; r++) acc[mt][nt][r] = 0.f;

    const int NIT = K / GBK;   // 4

    auto issue = [&](int it, int stage) {
        const int k0 = it * GBK;
#pragma unroll
        for (int l = 0; l < 4; l++) {
            int idx = tid + l * 256;   // 0..1023
            int r = idx >> 3;          // 0..127
            int c = idx & 7;           // 16B chunk (8 halves)
            cp16(sAu + ((stage * GBM + r) * PADH + c * 8) * 2,
                 A + (m0 + r) * K + k0 + c * 8);
            cp16(sBu + ((stage * GBN + r) * PADH + c * 8) * 2,
                 W + (n0 + r) * K + k0 + c * 8);
        }
        asm volatile("cp.async.commit_group;" ::: "memory");
    };

    issue(0, 0);
    issue(1, 1);

    // ldmatrix lane-derived offsets
    const int i8 = lane & 7;
    const int sub = lane >> 3;                 // 0..3
    const int arow = ((sub & 1) << 3) + i8;    // + wm*64 + mt*16
    const int acol = (sub >> 1) << 3;          // + ks
    const int brow = i8;                       // + wn*32 + nt*8
    const int bcol = (sub & 1) << 3;           // + ks

    for (int it = 0; it < NIT; ++it) {
        if (it + 1 < NIT)
            asm volatile("cp.async.wait_group 1;" ::: "memory");
        else
            asm volatile("cp.async.wait_group 0;" ::: "memory");
        __syncthreads();

        if (it + 2 < NIT) issue(it + 2, (it + 2) % NSTAGE);

        const int st = it % NSTAGE;
        const uint32_t aBase = sAu + ((st * GBM + wm * 64 + arow) * PADH + acol) * 2;
        const uint32_t bBase = sBu + ((st * GBN + wn * 32 + brow) * PADH + bcol) * 2;

        uint32_t af[2][4][4], bf[2][4][2];
        // preload ks=0 fragments
#pragma unroll
        for (int mt = 0; mt < 4; mt++)
            ldsm4(af[0][mt], aBase + (mt * 16 * PADH) * 2);
#pragma unroll
        for (int nt = 0; nt < 4; nt++)
            ldsm2(bf[0][nt], bBase + (nt * 8 * PADH) * 2);

#pragma unroll
        for (int s = 0; s < 4; s++) {   // 4 k16 steps in GBK=64
            const int cur = s & 1, nxt = cur ^ 1;
            if (s < 3) {
#pragma unroll
                for (int mt = 0; mt < 4; mt++)
                    ldsm4(af[nxt][mt], aBase + (mt * 16 * PADH + (s + 1) * 16) * 2);
#pragma unroll
                for (int nt = 0; nt < 4; nt++)
                    ldsm2(bf[nxt][nt], bBase + (nt * 8 * PADH + (s + 1) * 16) * 2);
            }
#pragma unroll
            for (int mt = 0; mt < 4; mt++)
#pragma unroll
                for (int nt = 0; nt < 4; nt++)
                    mma16816(acc[mt][nt], af[cur][mt], bf[cur][nt]);
        }
    }

    __syncthreads();

    // Epilogue with fused bias; OutT = float or __half
#pragma unroll
    for (int mt = 0; mt < 4; mt++) {
        long r0 = m0 + wm * 64 + mt * 16 + (lane >> 2);
#pragma unroll
        for (int nt = 0; nt < 4; nt++) {
            long c = n0 + wn * 32 + nt * 8 + 2 * (lane & 3);
            float2 b2 = *reinterpret_cast<const float2*>(&bias[c]);
            float v00 = acc[mt][nt][0] + b2.x, v01 = acc[mt][nt][1] + b2.y;
            float v10 = acc[mt][nt][2] + b2.x, v11 = acc[mt][nt][3] + b2.y;
            if (sizeof(OutT) == 4) {
                float2* p0 = reinterpret_cast<float2*>((float*)C + r0 * N + c);
                float2* p1 = reinterpret_cast<float2*>((float*)C + (r0 + 8) * N + c);
                *p0 = make_float2(v00, v01);
                *p1 = make_float2(v10, v11);
            } else {
                *reinterpret_cast<uint32_t*>((__half*)C + r0 * N + c) = packh2(v00, v01);
                *reinterpret_cast<uint32_t*>((__half*)C + (r0 + 8) * N + c) = packh2(v10, v11);
            }
        }
    }
}

// ---------------------------------------------------------------------------
// Tensor-core window attention. One block per window; 512 threads = 16 warps;
// warp = (head, query-half of 32 rows). K and V both stored row-major
// [head][token][d] in smem; K fragments via ldsm4, V via ldsm4.trans
// (no scalar transpose). fp32 softmax on fragments, unnormalized P,
// 1/sum in epilogue. y out fp16.
// smem: Ks[8][64][40] + Vs[8][64][40] (40960B each) + bt[225*8]f32 (7200B)
// ---------------------------------------------------------------------------
#define ATT_SMEM (40960 + 40960 + 7200)

__global__ __launch_bounds__(512)
void win_attn_mma_kernel(const __half* __restrict__ qkv,
                         const float* __restrict__ bias_table,
                         __half* __restrict__ y) {
    extern __shared__ char smraw[];
    __half* Ks = reinterpret_cast<__half*>(smraw);            // [8][64][40]
    __half* Vs = reinterpret_cast<__half*>(smraw + 40960);    // [8][64][40]
    float* bt = reinterpret_cast<float*>(smraw + 40960 + 40960);

    const uint32_t ksu = (uint32_t)__cvta_generic_to_shared(Ks);
    const uint32_t vsu = (uint32_t)__cvta_generic_to_shared(Vs);

    const int blk = blockIdx.x;
    const int wx = blk & 31, wy = (blk >> 5) & 31, bb = blk >> 10;
    const int tid = threadIdx.x;
    const size_t tokbase = ((size_t)bb << 16) + (size_t)wy * 8 * 256 + wx * 8;

    // ---- stage K and V (both coalesced uint4) ----
#pragma unroll
    for (int l = 0; l < 4; l++) {
        int idx = tid + l * 512;       // 0..2047
        int t = idx >> 5;              // token in window
        int u = idx & 31;              // uint4 within 256-half row
        int h = u >> 2;
        int d0 = (u & 3) * 8;
        size_t tok = tokbase + (size_t)(t >> 3) * 256 + (t & 7);
        const uint4* src = reinterpret_cast<const uint4*>(qkv + tok * 768);
        uint4 kk = src[32 + u];  // K region (+256 halves)
        *reinterpret_cast<uint4*>(&Ks[(h * 64 + t) * 40 + d0]) = kk;
        uint4 vv = src[64 + u];  // V region (+512 halves)
        *reinterpret_cast<uint4*>(&Vs[(h * 64 + t) * 40 + d0]) = vv;
    }
    for (int i = tid; i < 225 * 8; i += 512) bt[i] = bias_table[i];
    __syncthreads();

    const int warp = tid >> 5, lane = tid & 31;
    const int head = warp >> 1;
    const int q0 = (warp & 1) * 32;
    const int gr = lane >> 2;          // group row 0..7
    const int tc0 = (lane & 3) * 2;    // col pair base
    const int i8 = lane & 7;
    const int sub = lane >> 3;

    // ---- Q fragments (direct from global) ----
    int rowA[2], rowB[2];
    size_t tokA[2], tokB[2];
    uint32_t qf[2][2][4];
#pragma unroll
    for (int mi = 0; mi < 2; mi++) {
        rowA[mi] = q0 + mi * 16 + gr;
        rowB[mi] = rowA[mi] + 8;
        tokA[mi] = tokbase + (size_t)(rowA[mi] >> 3) * 256 + (rowA[mi] & 7);
        tokB[mi] = tokbase + (size_t)(rowB[mi] >> 3) * 256 + (rowB[mi] & 7);
#pragma unroll
        for (int kt = 0; kt < 2; kt++) {
            int dbase = head * 32 + kt * 16 + tc0;
            qf[mi][kt][0] = *reinterpret_cast<const uint32_t*>(qkv + tokA[mi] * 768 + dbase);
            qf[mi][kt][1] = *reinterpret_cast<const uint32_t*>(qkv + tokB[mi] * 768 + dbase);
            qf[mi][kt][2] = *reinterpret_cast<const uint32_t*>(qkv + tokA[mi] * 768 + dbase + 8);
            qf[mi][kt][3] = *reinterpret_cast<const uint32_t*>(qkv + tokB[mi] * 768 + dbase + 8);
        }
    }

    // ---- scores S = Q K^T  (K B-fragments: one ldsm4 per key-tile) ----
    float S[2][8][4];
#pragma unroll
    for (int mi = 0; mi < 2; mi++)
#pragma unroll
        for (int nj = 0; nj < 8; nj++)
#pragma unroll
            for (int r = 0; r < 4; r++) S[mi][nj][r] = 0.f;

    // lanes 0-7: rows nj*8+i8 col 0 (b0,kt0); 8-15: col 8 (b1,kt0);
    // 16-23: col 16 (b0,kt1); 24-31: col 24 (b1,kt1)
    const uint32_t kBase = ksu + ((head * 64 + i8) * 40 + sub * 8) * 2;
#pragma unroll
    for (int nj = 0; nj < 8; nj++) {
        uint32_t bf4[4];
        ldsm4(bf4, kBase + (nj * 8 * 40) * 2);
#pragma unroll
        for (int mi = 0; mi < 2; mi++)
#pragma unroll
            for (int kt = 0; kt < 2; kt++)
                mma16816(S[mi][nj], qf[mi][kt], bf4 + kt * 2);
    }

    // ---- scale + relative-position bias + softmax (unnormalized P) ----
    const float scale = 0.17677669529663687f; // 1/sqrt(32)
    float mx[2][2], sm[2][2];
#pragma unroll
    for (int mi = 0; mi < 2; mi++) {
        const int qiA = rowA[mi] >> 3, qjA = rowA[mi] & 7;
        const int qiB = rowB[mi] >> 3, qjB = rowB[mi] & 7;
        mx[mi][0] = -1e30f; mx[mi][1] = -1e30f;
#pragma unroll
        for (int nj = 0; nj < 8; nj++) {
            int relA = (qiA - nj + 7) * 15 + (qjA + 7 - tc0);
            int relB = (qiB - nj + 7) * 15 + (qjB + 7 - tc0);
            S[mi][nj][0] = S[mi][nj][0] * scale + bt[relA * 8 + head];
            S[mi][nj][1] = S[mi][nj][1] * scale + bt[(relA - 1) * 8 + head];
            S[mi][nj][2] = S[mi][nj][2] * scale + bt[relB * 8 + head];
            S[mi][nj][3] = S[mi][nj][3] * scale + bt[(relB - 1) * 8 + head];
            mx[mi][0] = fmaxf(mx[mi][0], fmaxf(S[mi][nj][0], S[mi][nj][1]));
            mx[mi][1] = fmaxf(mx[mi][1], fmaxf(S[mi][nj][2], S[mi][nj][3]));
        }
#pragma unroll
        for (int d = 1; d < 4; d <<= 1) {
            mx[mi][0] = fmaxf(mx[mi][0], __shfl_xor_sync(0xffffffffu, mx[mi][0], d));
            mx[mi][1] = fmaxf(mx[mi][1], __shfl_xor_sync(0xffffffffu, mx[mi][1], d));
        }
        sm[mi][0] = 0.f; sm[mi][1] = 0.f;
#pragma unroll
        for (int nj = 0; nj < 8; nj++) {
            S[mi][nj][0] = __expf(S[mi][nj][0] - mx[mi][0]);
            S[mi][nj][1] = __expf(S[mi][nj][1] - mx[mi][0]);
            S[mi][nj][2] = __expf(S[mi][nj][2] - mx[mi][1]);
            S[mi][nj][3] = __expf(S[mi][nj][3] - mx[mi][1]);
            sm[mi][0] += S[mi][nj][0] + S[mi][nj][1];
            sm[mi][1] += S[mi][nj][2] + S[mi][nj][3];
        }
#pragma unroll
        for (int d = 1; d < 4; d <<= 1) {
            sm[mi][0] += __shfl_xor_sync(0xffffffffu, sm[mi][0], d);
            sm[mi][1] += __shfl_xor_sync(0xffffffffu, sm[mi][1], d);
        }
    }

    // ---- pack P fragments (C->A layout trick), fp16 ----
    uint32_t pa[2][4][4];
#pragma unroll
    for (int mi = 0; mi < 2; mi++)
#pragma unroll
        for (int kt = 0; kt < 4; kt++) {
            pa[mi][kt][0] = packh2(S[mi][2 * kt][0], S[mi][2 * kt][1]);
            pa[mi][kt][1] = packh2(S[mi][2 * kt][2], S[mi][2 * kt][3]);
            pa[mi][kt][2] = packh2(S[mi][2 * kt + 1][0], S[mi][2 * kt + 1][1]);
            pa[mi][kt][3] = packh2(S[mi][2 * kt + 1][2], S[mi][2 * kt + 1][3]);
        }

    // ---- O = P * V  (V B-fragments via ldsm4.trans; rows = tokens) ----
    float O[2][4][4];
#pragma unroll
    for (int mi = 0; mi < 2; mi++)
#pragma unroll
        for (int dj = 0; dj < 4; dj++)
#pragma unroll
            for (int r = 0; r < 4; r++) O[mi][dj][r] = 0.f;

    const uint32_t vBase0 = vsu + ((head * 64 + lane) * 40) * 2;        // tokens 0-31
    const uint32_t vBase1 = vsu + ((head * 64 + 32 + lane) * 40) * 2;   // tokens 32-63
#pragma unroll
    for (int dj = 0; dj < 4; dj++) {
        uint32_t vb[8];   // [kt0 b0,b1, kt1 b0,b1] then kt2,kt3
        ldsm4t(vb, vBase0 + (dj * 8) * 2);
        ldsm4t(vb + 4, vBase1 + (dj * 8) * 2);
#pragma unroll
        for (int kt = 0; kt < 4; kt++)
#pragma unroll
            for (int mi = 0; mi < 2; mi++)
                mma16816(O[mi][dj], pa[mi][kt], vb + kt * 2);
    }

    // ---- epilogue: scale by 1/sum, write fp16 y ----
#pragma unroll
    for (int mi = 0; mi < 2; mi++) {
        const float rsA = 1.f / sm[mi][0];
        const float rsB = 1.f / sm[mi][1];
        __half* ypA = y + tokA[mi] * DIMC + head * 32 + tc0;
        __half* ypB = y + tokB[mi] * DIMC + head * 32 + tc0;
#pragma unroll
        for (int dj = 0; dj < 4; dj++) {
            *reinterpret_cast<uint32_t*>(ypA + dj * 8) =
                packh2(O[mi][dj][0] * rsA, O[mi][dj][1] * rsA);
            *reinterpret_cast<uint32_t*>(ypB + dj * 8) =
                packh2(O[mi][dj][2] * rsB, O[mi][dj][3] * rsB);
        }
    }
}

// ---------------------------------------------------------------------------
extern "C" void kernel_launch(void* const* d_in, const int* in_sizes, int n_in,
                              void* d_out, int out_size) {
    // metadata order: x, h, w, wqkv_w, wqkv_b, wp_w, wp_b, bias_table
    const float* x = (const float*)d_in[0];
    const float* wqkv_w = (const float*)d_in[3];
    const float* wqkv_b = (const float*)d_in[4];
    const float* wp_w = (const float*)d_in[5];
    const float* wp_b = (const float*)d_in[6];
    const float* bias_table = (const float*)d_in[7];
    float* out = (float*)d_out;

    const int M = in_sizes[0] / DIMC;  // b * 65536
    const int b = M / 65536;

    __half *qkvh, *ybuf, *xh, *wqkvh, *wph;
    cudaGetSymbolAddress((void**)&qkvh, g_qkvh);
    cudaGetSymbolAddress((void**)&ybuf, g_y);
    cudaGetSymbolAddress((void**)&xh, g_xh);
    cudaGetSymbolAddress((void**)&wqkvh, g_wqkvh);
    cudaGetSymbolAddress((void**)&wph, g_wph);

    cudaFuncSetAttribute(win_attn_mma_kernel,
                         cudaFuncAttributeMaxDynamicSharedMemorySize, ATT_SMEM);
    cudaFuncSetAttribute(gemm_f16_kernel<__half>,
                         cudaFuncAttributeMaxDynamicSharedMemorySize, GEMM_SMEM);
    cudaFuncSetAttribute(gemm_f16_kernel<float>,
                         cudaFuncAttributeMaxDynamicSharedMemorySize, GEMM_SMEM);

    // 0) fp16 conversion of x and both weight matrices
    {
        int n4 = M * (DIMC / 4);
        f2h_convert_kernel<<<(n4 + 255) / 256, 256>>>(x, xh, n4);
        int w4 = 768 * (DIMC / 4);
        f2h_convert_kernel<<<(w4 + 255) / 256, 256>>>(wqkv_w, wqkvh, w4);
        int p4 = DIMC * (DIMC / 4);
        f2h_convert_kernel<<<(p4 + 255) / 256, 256>>>(wp_w, wph, p4);
    }
    // 1) QKV projection -> fp16 qkv
    {
        dim3 grid(768 / GBN, M / GBM);
        gemm_f16_kernel<__half><<<grid, 256, GEMM_SMEM>>>(xh, wqkvh, wqkv_b,
                                                          qkvh, M, 768, DIMC);
    }
    // 2) Tensor-core window attention (one block per window)
    {
        int nblocks = b * 32 * 32;
        win_attn_mma_kernel<<<nblocks, 512, ATT_SMEM>>>(qkvh, bias_table, ybuf);
    }
    // 3) Output projection -> fp32 out
    {
        dim3 grid(DIMC / GBN, M / GBM);
        gemm_f16_kernel<float><<<grid, 256, GEMM_SMEM>>>(ybuf, wph, wp_b, out,
                                                         M, DIMC, DIMC);
    }
}

// round 12
// speedup vs baseline: 1.3603x; 1.3603x over previous
#include <cuda_runtime.h>
#include <cuda_fp16.h>
#include <math.h>
#include <stdint.h>

// Problem constants (fixed: b=2, h=w=256, DIM=256, HEADS=8, 8x8 windows)
#define DIMC 256
#define NHEADS 8
#define HD 32
#define WSZ 64
#define MAXB 2

// Scratch (allocation-free rule: __device__ globals)
__device__ __half g_qkvh[(size_t)MAXB * 65536 * 768]; // QKV output (fp16)
__device__ __half g_y[(size_t)MAXB * 65536 * 256];    // attention output (fp16)
__device__ __half g_xh[(size_t)MAXB * 65536 * 256];   // x in fp16
__device__ __half g_wqkvh[768 * 256];                 // wqkv_w fp16
__device__ __half g_wph[256 * 256];                   // wp_w fp16

// ---------------------------------------------------------------------------
// helpers
// ---------------------------------------------------------------------------
__device__ __forceinline__ void cp16(uint32_t saddr, const void* g) {
    asm volatile("cp.async.cg.shared.global [%0], [%1], 16;" :: "r"(saddr), "l"(g));
}
__device__ __forceinline__ void mma16816(float* d, const uint32_t* a,
                                         const uint32_t* b) {
    asm volatile(
        "mma.sync.aligned.m16n8k16.row.col.f32.f16.f16.f32 "
        "{%0,%1,%2,%3}, {%4,%5,%6,%7}, {%8,%9}, {%0,%1,%2,%3};"
        : "+f"(d[0]), "+f"(d[1]), "+f"(d[2]), "+f"(d[3])
        : "r"(a[0]), "r"(a[1]), "r"(a[2]), "r"(a[3]), "r"(b[0]), "r"(b[1]));
}
__device__ __forceinline__ void ldsm4(uint32_t* r, uint32_t addr) {
    asm volatile("ldmatrix.sync.aligned.m8n8.x4.shared.b16 {%0,%1,%2,%3}, [%4];"
                 : "=r"(r[0]), "=r"(r[1]), "=r"(r[2]), "=r"(r[3]) : "r"(addr));
}
__device__ __forceinline__ void ldsm4t(uint32_t* r, uint32_t addr) {
    asm volatile("ldmatrix.sync.aligned.m8n8.x4.trans.shared.b16 {%0,%1,%2,%3}, [%4];"
                 : "=r"(r[0]), "=r"(r[1]), "=r"(r[2]), "=r"(r[3]) : "r"(addr));
}
__device__ __forceinline__ void ldsm2(uint32_t* r, uint32_t addr) {
    asm volatile("ldmatrix.sync.aligned.m8n8.x2.shared.b16 {%0,%1}, [%2];"
                 : "=r"(r[0]), "=r"(r[1]) : "r"(addr));
}
__device__ __forceinline__ uint32_t packh2(float x, float y) {
    __half2 h = __floats2half2_rn(x, y);
    return *reinterpret_cast<uint32_t*>(&h);
}

// fp32 -> fp16 convert
__global__ void f2h_convert_kernel(const float* __restrict__ in,
                                   __half* __restrict__ out, int n4) {
    int i = blockIdx.x * blockDim.x + threadIdx.x;
    if (i < n4) {
        float4 v = reinterpret_cast<const float4*>(in)[i];
        uint2 p;
        p.x = packh2(v.x, v.y);
        p.y = packh2(v.z, v.w);
        reinterpret_cast<uint2*>(out)[i] = p;
    }
}

// ---------------------------------------------------------------------------
// FP16 tensor-core GEMM, fp32 accum, fused bias, templated output type:
//   C[M,N] = A[M,K](f16) * W[N,K](f16)^T + bias[N](f32)
// 128x128x32 tile, 8 warps (2x4), warp tile 64x32 via 4x4 m16n8k16.
// 3-stage cp.async ring, ldmatrix fragment loads, 1 barrier per K-iter.
// (R10 configuration — measured 225us on GEMM1.)
// ---------------------------------------------------------------------------
#define GBM 128
#define GBN 128
#define GBK 32
#define PADH 40
#define NSTAGE 3
#define GEMM_SMEM (NSTAGE * (GBM + GBN) * PADH * 2)  // 61440 bytes

template <typename OutT>
__global__ __launch_bounds__(256, 2)
void gemm_f16_kernel(const __half* __restrict__ A, const __half* __restrict__ W,
                     const float* __restrict__ bias, OutT* __restrict__ C,
                     int M, int N, int K) {
    extern __shared__ __half smh[];
    __half* As = smh;                          // [NSTAGE][GBM][PADH]
    __half* Bs = smh + NSTAGE * GBM * PADH;    // [NSTAGE][GBN][PADH]

    const int tid = threadIdx.x;
    const int lane = tid & 31;
    const int warp = tid >> 5;
    const int wm = warp >> 2;  // 0..1
    const int wn = warp & 3;   // 0..3
    const long m0 = (long)blockIdx.y * GBM;
    const long n0 = (long)blockIdx.x * GBN;

    const uint32_t sAu = (uint32_t)__cvta_generic_to_shared(As);
    const uint32_t sBu = (uint32_t)__cvta_generic_to_shared(Bs);

    float acc[4][4][4];
#pragma unroll
    for (int mt = 0; mt < 4; mt++)
#pragma unroll
        for (int nt = 0; nt < 4; nt++)
#pragma unroll
            for (int r = 0; r < 4; r++) acc[mt][nt][r] = 0.f;

    const int NIT = K / GBK;

    auto issue = [&](int it, int stage) {
        const int k0 = it * GBK;
#pragma unroll
        for (int l = 0; l < 2; l++) {
            int idx = tid + l * 256;   // 0..511
            int r = idx >> 2;          // 0..127
            int c = idx & 3;           // 16B chunk
            cp16(sAu + ((stage * GBM + r) * PADH + c * 8) * 2,
                 A + (m0 + r) * K + k0 + c * 8);
            cp16(sBu + ((stage * GBN + r) * PADH + c * 8) * 2,
                 W + (n0 + r) * K + k0 + c * 8);
        }
        asm volatile("cp.async.commit_group;" ::: "memory");
    };

    issue(0, 0);
    issue(1, 1);

    // ldmatrix lane-derived offsets
    const int i8 = lane & 7;
    const int sub = lane >> 3;                 // 0..3
    const int arow = ((sub & 1) << 3) + i8;    // + wm*64 + mt*16
    const int acol = (sub >> 1) << 3;          // + ks
    const int brow = i8;                       // + wn*32 + nt*8  (x2: lanes 0-15)
    const int bcol = (sub & 1) << 3;           // + ks

    for (int it = 0; it < NIT; ++it) {
        if (it + 1 < NIT)
            asm volatile("cp.async.wait_group 1;" ::: "memory");
        else
            asm volatile("cp.async.wait_group 0;" ::: "memory");
        __syncthreads();

        if (it + 2 < NIT) issue(it + 2, (it + 2) % NSTAGE);

        const int st = it % NSTAGE;
        const uint32_t aBase = sAu + ((st * GBM + wm * 64 + arow) * PADH) * 2;
        const uint32_t bBase = sBu + ((st * GBN + wn * 32 + brow) * PADH) * 2;

#pragma unroll
        for (int ks = 0; ks < GBK; ks += 16) {
            uint32_t af[4][4], bf[4][2];
#pragma unroll
            for (int mt = 0; mt < 4; mt++)
                ldsm4(af[mt], aBase + (mt * 16 * PADH + ks + acol) * 2);
#pragma unroll
            for (int nt = 0; nt < 4; nt++)
                ldsm2(bf[nt], bBase + (nt * 8 * PADH + ks + bcol) * 2);
#pragma unroll
            for (int mt = 0; mt < 4; mt++)
#pragma unroll
                for (int nt = 0; nt < 4; nt++)
                    mma16816(acc[mt][nt], af[mt], bf[nt]);
        }
    }

    __syncthreads();

    // Epilogue with fused bias; OutT = float or __half
#pragma unroll
    for (int mt = 0; mt < 4; mt++) {
        long r0 = m0 + wm * 64 + mt * 16 + (lane >> 2);
#pragma unroll
        for (int nt = 0; nt < 4; nt++) {
            long c = n0 + wn * 32 + nt * 8 + 2 * (lane & 3);
            float2 b2 = *reinterpret_cast<const float2*>(&bias[c]);
            float v00 = acc[mt][nt][0] + b2.x, v01 = acc[mt][nt][1] + b2.y;
            float v10 = acc[mt][nt][2] + b2.x, v11 = acc[mt][nt][3] + b2.y;
            if (sizeof(OutT) == 4) {
                float2* p0 = reinterpret_cast<float2*>((float*)C + r0 * N + c);
                float2* p1 = reinterpret_cast<float2*>((float*)C + (r0 + 8) * N + c);
                *p0 = make_float2(v00, v01);
                *p1 = make_float2(v10, v11);
            } else {
                *reinterpret_cast<uint32_t*>((__half*)C + r0 * N + c) = packh2(v00, v01);
                *reinterpret_cast<uint32_t*>((__half*)C + (r0 + 8) * N + c) = packh2(v10, v11);
            }
        }
    }
}

// ---------------------------------------------------------------------------
// Tensor-core window attention (R11 version — measured ~30us better than R10).
// One block per window; 512 threads = 16 warps; warp = (head, query-half).
// K and V both stored row-major [head][token][d] in smem; K fragments via
// ldsm4, V via ldsm4.trans. fp32 softmax on fragments, unnormalized P,
// 1/sum in epilogue. y out fp16.
// smem: Ks[8][64][40] + Vs[8][64][40] (40960B each) + bt[225*8]f32 (7200B)
// ---------------------------------------------------------------------------
#define ATT_SMEM (40960 + 40960 + 7200)

__global__ __launch_bounds__(512)
void win_attn_mma_kernel(const __half* __restrict__ qkv,
                         const float* __restrict__ bias_table,
                         __half* __restrict__ y) {
    extern __shared__ char smraw[];
    __half* Ks = reinterpret_cast<__half*>(smraw);            // [8][64][40]
    __half* Vs = reinterpret_cast<__half*>(smraw + 40960);    // [8][64][40]
    float* bt = reinterpret_cast<float*>(smraw + 40960 + 40960);

    const uint32_t ksu = (uint32_t)__cvta_generic_to_shared(Ks);
    const uint32_t vsu = (uint32_t)__cvta_generic_to_shared(Vs);

    const int blk = blockIdx.x;
    const int wx = blk & 31, wy = (blk >> 5) & 31, bb = blk >> 10;
    const int tid = threadIdx.x;
    const size_t tokbase = ((size_t)bb << 16) + (size_t)wy * 8 * 256 + wx * 8;

    // ---- stage K and V (both coalesced uint4) ----
#pragma unroll
    for (int l = 0; l < 4; l++) {
        int idx = tid + l * 512;       // 0..2047
        int t = idx >> 5;              // token in window
        int u = idx & 31;              // uint4 within 256-half row
        int h = u >> 2;
        int d0 = (u & 3) * 8;
        size_t tok = tokbase + (size_t)(t >> 3) * 256 + (t & 7);
        const uint4* src = reinterpret_cast<const uint4*>(qkv + tok * 768);
        uint4 kk = src[32 + u];  // K region (+256 halves)
        *reinterpret_cast<uint4*>(&Ks[(h * 64 + t) * 40 + d0]) = kk;
        uint4 vv = src[64 + u];  // V region (+512 halves)
        *reinterpret_cast<uint4*>(&Vs[(h * 64 + t) * 40 + d0]) = vv;
    }
    for (int i = tid; i < 225 * 8; i += 512) bt[i] = bias_table[i];
    __syncthreads();

    const int warp = tid >> 5, lane = tid & 31;
    const int head = warp >> 1;
    const int q0 = (warp & 1) * 32;
    const int gr = lane >> 2;          // group row 0..7
    const int tc0 = (lane & 3) * 2;    // col pair base
    const int i8 = lane & 7;
    const int sub = lane >> 3;

    // ---- Q fragments (direct from global) ----
    int rowA[2], rowB[2];
    size_t tokA[2], tokB[2];
    uint32_t qf[2][2][4];
#pragma unroll
    for (int mi = 0; mi < 2; mi++) {
        rowA[mi] = q0 + mi * 16 + gr;
        rowB[mi] = rowA[mi] + 8;
        tokA[mi] = tokbase + (size_t)(rowA[mi] >> 3) * 256 + (rowA[mi] & 7);
        tokB[mi] = tokbase + (size_t)(rowB[mi] >> 3) * 256 + (rowB[mi] & 7);
#pragma unroll
        for (int kt = 0; kt < 2; kt++) {
            int dbase = head * 32 + kt * 16 + tc0;
            qf[mi][kt][0] = *reinterpret_cast<const uint32_t*>(qkv + tokA[mi] * 768 + dbase);
            qf[mi][kt][1] = *reinterpret_cast<const uint32_t*>(qkv + tokB[mi] * 768 + dbase);
            qf[mi][kt][2] = *reinterpret_cast<const uint32_t*>(qkv + tokA[mi] * 768 + dbase + 8);
            qf[mi][kt][3] = *reinterpret_cast<const uint32_t*>(qkv + tokB[mi] * 768 + dbase + 8);
        }
    }

    // ---- scores S = Q K^T  (K B-fragments: one ldsm4 per key-tile) ----
    float S[2][8][4];
#pragma unroll
    for (int mi = 0; mi < 2; mi++)
#pragma unroll
        for (int nj = 0; nj < 8; nj++)
#pragma unroll
            for (int r = 0; r < 4; r++) S[mi][nj][r] = 0.f;

    const uint32_t kBase = ksu + ((head * 64 + i8) * 40 + sub * 8) * 2;
#pragma unroll
    for (int nj = 0; nj < 8; nj++) {
        uint32_t bf4[4];
        ldsm4(bf4, kBase + (nj * 8 * 40) * 2);
#pragma unroll
        for (int mi = 0; mi < 2; mi++)
#pragma unroll
            for (int kt = 0; kt < 2; kt++)
                mma16816(S[mi][nj], qf[mi][kt], bf4 + kt * 2);
    }

    // ---- scale + relative-position bias + softmax (unnormalized P) ----
    const float scale = 0.17677669529663687f; // 1/sqrt(32)
    float mx[2][2], sm[2][2];
#pragma unroll
    for (int mi = 0; mi < 2; mi++) {
        const int qiA = rowA[mi] >> 3, qjA = rowA[mi] & 7;
        const int qiB = rowB[mi] >> 3, qjB = rowB[mi] & 7;
        mx[mi][0] = -1e30f; mx[mi][1] = -1e30f;
#pragma unroll
        for (int nj = 0; nj < 8; nj++) {
            int relA = (qiA - nj + 7) * 15 + (qjA + 7 - tc0);
            int relB = (qiB - nj + 7) * 15 + (qjB + 7 - tc0);
            S[mi][nj][0] = S[mi][nj][0] * scale + bt[relA * 8 + head];
            S[mi][nj][1] = S[mi][nj][1] * scale + bt[(relA - 1) * 8 + head];
            S[mi][nj][2] = S[mi][nj][2] * scale + bt[relB * 8 + head];
            S[mi][nj][3] = S[mi][nj][3] * scale + bt[(relB - 1) * 8 + head];
            mx[mi][0] = fmaxf(mx[mi][0], fmaxf(S[mi][nj][0], S[mi][nj][1]));
            mx[mi][1] = fmaxf(mx[mi][1], fmaxf(S[mi][nj][2], S[mi][nj][3]));
        }
#pragma unroll
        for (int d = 1; d < 4; d <<= 1) {
            mx[mi][0] = fmaxf(mx[mi][0], __shfl_xor_sync(0xffffffffu, mx[mi][0], d));
            mx[mi][1] = fmaxf(mx[mi][1], __shfl_xor_sync(0xffffffffu, mx[mi][1], d));
        }
        sm[mi][0] = 0.f; sm[mi][1] = 0.f;
#pragma unroll
        for (int nj = 0; nj < 8; nj++) {
            S[mi][nj][0] = __expf(S[mi][nj][0] - mx[mi][0]);
            S[mi][nj][1] = __expf(S[mi][nj][1] - mx[mi][0]);
            S[mi][nj][2] = __expf(S[mi][nj][2] - mx[mi][1]);
            S[mi][nj][3] = __expf(S[mi][nj][3] - mx[mi][1]);
            sm[mi][0] += S[mi][nj][0] + S[mi][nj][1];
            sm[mi][1] += S[mi][nj][2] + S[mi][nj][3];
        }
#pragma unroll
        for (int d = 1; d < 4; d <<= 1) {
            sm[mi][0] += __shfl_xor_sync(0xffffffffu, sm[mi][0], d);
            sm[mi][1] += __shfl_xor_sync(0xffffffffu, sm[mi][1], d);
        }
    }

    // ---- pack P fragments (C->A layout trick), fp16 ----
    uint32_t pa[2][4][4];
#pragma unroll
    for (int mi = 0; mi < 2; mi++)
#pragma unroll
        for (int kt = 0; kt < 4; kt++) {
            pa[mi][kt][0] = packh2(S[mi][2 * kt][0], S[mi][2 * kt][1]);
            pa[mi][kt][1] = packh2(S[mi][2 * kt][2], S[mi][2 * kt][3]);
            pa[mi][kt][2] = packh2(S[mi][2 * kt + 1][0], S[mi][2 * kt + 1][1]);
            pa[mi][kt][3] = packh2(S[mi][2 * kt + 1][2], S[mi][2 * kt + 1][3]);
        }

    // ---- O = P * V  (V B-fragments via ldsm4.trans; rows = tokens) ----
    float O[2][4][4];
#pragma unroll
    for (int mi = 0; mi < 2; mi++)
#pragma unroll
        for (int dj = 0; dj < 4; dj++)
#pragma unroll
            for (int r = 0; r < 4; r++) O[mi][dj][r] = 0.f;

    const uint32_t vBase0 = vsu + ((head * 64 + lane) * 40) * 2;        // tokens 0-31
    const uint32_t vBase1 = vsu + ((head * 64 + 32 + lane) * 40) * 2;   // tokens 32-63
#pragma unroll
    for (int dj = 0; dj < 4; dj++) {
        uint32_t vb[8];
        ldsm4t(vb, vBase0 + (dj * 8) * 2);
        ldsm4t(vb + 4, vBase1 + (dj * 8) * 2);
#pragma unroll
        for (int kt = 0; kt < 4; kt++)
#pragma unroll
            for (int mi = 0; mi < 2; mi++)
                mma16816(O[mi][dj], pa[mi][kt], vb + kt * 2);
    }

    // ---- epilogue: scale by 1/sum, write fp16 y ----
#pragma unroll
    for (int mi = 0; mi < 2; mi++) {
        const float rsA = 1.f / sm[mi][0];
        const float rsB = 1.f / sm[mi][1];
        __half* ypA = y + tokA[mi] * DIMC + head * 32 + tc0;
        __half* ypB = y + tokB[mi] * DIMC + head * 32 + tc0;
#pragma unroll
        for (int dj = 0; dj < 4; dj++) {
            *reinterpret_cast<uint32_t*>(ypA + dj * 8) =
                packh2(O[mi][dj][0] * rsA, O[mi][dj][1] * rsA);
            *reinterpret_cast<uint32_t*>(ypB + dj * 8) =
                packh2(O[mi][dj][2] * rsB, O[mi][dj][3] * rsB);
        }
    }
}

// ---------------------------------------------------------------------------
extern "C" void kernel_launch(void* const* d_in, const int* in_sizes, int n_in,
                              void* d_out, int out_size) {
    // metadata order: x, h, w, wqkv_w, wqkv_b, wp_w, wp_b, bias_table
    const float* x = (const float*)d_in[0];
    const float* wqkv_w = (const float*)d_in[3];
    const float* wqkv_b = (const float*)d_in[4];
    const float* wp_w = (const float*)d_in[5];
    const float* wp_b = (const float*)d_in[6];
    const float* bias_table = (const float*)d_in[7];
    float* out = (float*)d_out;

    const int M = in_sizes[0] / DIMC;  // b * 65536
    const int b = M / 65536;

    __half *qkvh, *ybuf, *xh, *wqkvh, *wph;
    cudaGetSymbolAddress((void**)&qkvh, g_qkvh);
    cudaGetSymbolAddress((void**)&ybuf, g_y);
    cudaGetSymbolAddress((void**)&xh, g_xh);
    cudaGetSymbolAddress((void**)&wqkvh, g_wqkvh);
    cudaGetSymbolAddress((void**)&wph, g_wph);

    cudaFuncSetAttribute(win_attn_mma_kernel,
                         cudaFuncAttributeMaxDynamicSharedMemorySize, ATT_SMEM);
    cudaFuncSetAttribute(gemm_f16_kernel<__half>,
                         cudaFuncAttributeMaxDynamicSharedMemorySize, GEMM_SMEM);
    cudaFuncSetAttribute(gemm_f16_kernel<float>,
                         cudaFuncAttributeMaxDynamicSharedMemorySize, GEMM_SMEM);

    // 0) fp16 conversion of x and both weight matrices
    {
        int n4 = M * (DIMC / 4);
        f2h_convert_kernel<<<(n4 + 255) / 256, 256>>>(x, xh, n4);
        int w4 = 768 * (DIMC / 4);
        f2h_convert_kernel<<<(w4 + 255) / 256, 256>>>(wqkv_w, wqkvh, w4);
        int p4 = DIMC * (DIMC / 4);
        f2h_convert_kernel<<<(p4 + 255) / 256, 256>>>(wp_w, wph, p4);
    }
    // 1) QKV projection -> fp16 qkv
    {
        dim3 grid(768 / GBN, M / GBM);
        gemm_f16_kernel<__half><<<grid, 256, GEMM_SMEM>>>(xh, wqkvh, wqkv_b,
                                                          qkvh, M, 768, DIMC);
    }
    // 2) Tensor-core window attention (one block per window)
    {
        int nblocks = b * 32 * 32;
        win_attn_mma_kernel<<<nblocks, 512, ATT_SMEM>>>(qkvh, bias_table, ybuf);
    }
    // 3) Output projection -> fp32 out
    {
        dim3 grid(DIMC / GBN, M / GBM);
        gemm_f16_kernel<float><<<grid, 256, GEMM_SMEM>>>(ybuf, wph, wp_b, out,
                                                         M, DIMC, DIMC);
    }
}